// round 16
// baseline (speedup 1.0000x reference)
#include <cuda_runtime.h>

#define P   128
#define NT  256
#define PT  132   // pitch for sT / sD (skewed)
#define PL  130   // pitch for Lsh

typedef unsigned long long u64;

struct __align__(16) Smem {
  float sT[P][PT];     // Theta (orig), later Theta+Delta (symmetric)
  float sD[P][PT];     // Tc buffer, later Delta (symmetric, zero diag)
  float Lsh[P][PL];    // L_w (127x127, row 127 zeroed)
  float rowA[2][PT];   // sweep pivot row k   (with [k]   -= 1)
  float rowB[2][PT];   // sweep pivot row k+1 (with [k+1] -= 1)
  // scan epoch vectors (double-buffered, gapped)
  float tv0[2][PT], dv0[2][PT], tv1[2][PT], dv1[2][PT];
  // scan basis vectors for lazy rank-4 update (double-buffered, gapped)
  float gsh0[2][PT];   // W row c0
  float uv0[2][PT];    // u0 with [c0]-=1
  float gshB[2][PT];   // W row c1
  float uvT[2][PT];    // utilde with [c1]-=1
  float red[2][6][8];  // 6 reductions x 8 warps
  float pt[2][8];      // point values
  float diag[P];
};

// gapped index: halves offset by +4 floats -> warp halves hit different banks
__device__ __forceinline__ int VIDX(int x) { return x + ((x >> 6) << 2); }

__device__ __forceinline__ u64 pk2s(float x) {
  u64 r; asm("mov.b64 %0,{%1,%1};" : "=l"(r) : "f"(x)); return r;
}
__device__ __forceinline__ u64 pk2(float x, float y) {
  u64 r; asm("mov.b64 %0,{%1,%2};" : "=l"(r) : "f"(x), "f"(y)); return r;
}
__device__ __forceinline__ float2 up2(u64 a) {
  float2 f; asm("mov.b64 {%0,%1},%2;" : "=f"(f.x), "=f"(f.y) : "l"(a)); return f;
}
__device__ __forceinline__ u64 f2ma(u64 a, u64 b, u64 c) {
  u64 d; asm("fma.rn.f32x2 %0,%1,%2,%3;" : "=l"(d) : "l"(a), "l"(b), "l"(c));
  return d;
}
__device__ __forceinline__ u64 f2add(u64 a, u64 b) {
  u64 d; asm("add.rn.f32x2 %0,%1,%2;" : "=l"(d) : "l"(a), "l"(b));
  return d;
}
__device__ __forceinline__ float frcp(float x) {
  float r; asm("rcp.approx.f32 %0,%1;" : "=f"(r) : "f"(x)); return r;
}

__global__ void __launch_bounds__(NT, 1)
spod_kernel(const float* __restrict__ Theta,
            const float* __restrict__ Lw,
            float* __restrict__ Out)
{
  extern __shared__ __align__(16) float smraw[];
  Smem* sm = reinterpret_cast<Smem*>(smraw);

  const int tid = threadIdx.x;
  const int b   = blockIdx.x;
  const int i   = tid >> 1;      // row owned by this thread
  const int jh  = tid & 1;       // which 64-column half
  const int j0  = jh << 6;       // 0 or 64
  const int vb  = jh ? 68 : 0;   // VIDX(j0)

  const float* Tin = Theta + (size_t)b * (P * P);

  // ---------------- Phase A: load Theta, L_w (coalesced) ----------------
  for (int idx = tid; idx < P * P; idx += NT)
    sm->sT[idx >> 7][idx & 127] = Tin[idx];
  for (int idx = tid; idx < 127 * 127; idx += NT) {
    int r = idx / 127;
    sm->Lsh[r][idx - r * 127] = Lw[idx];
  }
  if (tid < PL) sm->Lsh[127][tid] = 0.0f;
  if (tid < PT) {   // zero parity-1 basis arrays for epoch 0
    sm->gsh0[1][tid] = 0.0f; sm->uv0[1][tid] = 0.0f;
    sm->gshB[1][tid] = 0.0f; sm->uvT[1][tid] = 0.0f;
  }
  __syncthreads();

  // ---------------- Phase B0: Tc[m][c] = Theta[m + (m>=c)][c] ----------------
  for (int idx = tid; idx < 127 * P; idx += NT) {
    int m = idx >> 7, c = idx & 127;
    sm->sD[m][c] = sm->sT[m + (m >= c)][c];
  }
  __syncthreads();

  // ---------------- Phase B1: Y = Lsh @ Tc (packed f32x2) ----------------
  const int tj = tid >> 4, ti = tid & 15;
  const int jr = tj * 8, ic = ti * 8;
  u64 acc2[8][4];
  #pragma unroll
  for (int r = 0; r < 8; ++r)
    #pragma unroll
    for (int s = 0; s < 4; ++s) acc2[r][s] = 0ULL;

  #pragma unroll 1
  for (int m = 0; m < 127; ++m) {
    ulonglong2 ta = *(const ulonglong2*)&sm->sD[m][ic];
    ulonglong2 tb = *(const ulonglong2*)&sm->sD[m][ic + 4];
    #pragma unroll
    for (int r = 0; r < 8; ++r) {
      u64 lr = pk2s(sm->Lsh[jr + r][m]);
      acc2[r][0] = f2ma(lr, ta.x, acc2[r][0]);
      acc2[r][1] = f2ma(lr, ta.y, acc2[r][1]);
      acc2[r][2] = f2ma(lr, tb.x, acc2[r][2]);
      acc2[r][3] = f2ma(lr, tb.y, acc2[r][3]);
    }
  }
  __syncthreads();

  // ---------------- Phase B2: Delta (symmetric) into sD ----------------
  #pragma unroll
  for (int r = 0; r < 8; ++r) {
    int j = jr + r;
    #pragma unroll
    for (int s = 0; s < 4; ++s) {
      float2 f = up2(acc2[r][s]);
      int i0 = ic + 2 * s, i1 = i0 + 1;
      if (j < i0) { float d0 = f.x - sm->sT[j][i0]; sm->sD[i0][j] = d0; sm->sD[j][i0] = d0; }
      if (j < i1) { float d1 = f.y - sm->sT[j][i1]; sm->sD[i1][j] = d1; sm->sD[j][i1] = d1; }
    }
  }
  if (tid < P) sm->sD[tid][tid] = 0.0f;
  __syncthreads();

  // ---------------- Phase C: W = inv(Theta), 2-pivot blocked sweep ----------------
  u64 W2[32];
  #pragma unroll
  for (int t = 0; t < 16; ++t) {
    ulonglong2 v = *(const ulonglong2*)&sm->sT[i][j0 + 4 * t];
    W2[2 * t] = v.x; W2[2 * t + 1] = v.y;
  }

  #pragma unroll 1
  for (int k = 0; k < P; k += 2) {
    const int buf = (k >> 1) & 1;
    if (i == k || i == k + 1) {
      float* dst = (i == k) ? sm->rowA[buf] : sm->rowB[buf];
      #pragma unroll
      for (int t = 0; t < 16; ++t) {
        ulonglong2 o; o.x = W2[2 * t]; o.y = W2[2 * t + 1];
        *(ulonglong2*)&dst[vb + 4 * t] = o;
      }
      if ((i >> 6) == jh)            // my half holds column i: [i] -= 1 fixup
        dst[VIDX(i)] -= 1.0f;
    }
    __syncthreads();

    float a_k  = sm->rowA[buf][VIDX(k)];      // d00 - 1
    float a_k1 = sm->rowA[buf][VIDX(k + 1)];  // d01
    float b_k1 = sm->rowB[buf][VIDX(k + 1)];  // d11 - 1
    float d00 = a_k + 1.0f, d01 = a_k1, d11 = b_k1 + 1.0f;
    float rdet = frcp(fmaf(d00, d11, -d01 * d01));
    float i00 = d11 * rdet, i01 = -d01 * rdet, i11 = d00 * rdet;
    float c1w = sm->rowA[buf][VIDX(i)];
    float c2w = sm->rowB[buf][VIDX(i)];
    float g1 = fmaf(c1w, i00, c2w * i01);
    float g2 = fmaf(c1w, i01, c2w * i11);
    u64 ng1 = pk2s(-g1), ng2 = pk2s(-g2);
    #pragma unroll
    for (int t = 0; t < 16; ++t) {
      ulonglong2 rA = *(const ulonglong2*)&sm->rowA[buf][vb + 4 * t];
      ulonglong2 rB = *(const ulonglong2*)&sm->rowB[buf][vb + 4 * t];
      W2[2 * t]     = f2ma(ng2, rB.x, f2ma(ng1, rA.x, W2[2 * t]));
      W2[2 * t + 1] = f2ma(ng2, rB.y, f2ma(ng1, rA.y, W2[2 * t + 1]));
    }
  }

  // negate (sweep gives -A^{-1}), then fix the constant +2 pivot-diag error
  #pragma unroll
  for (int t = 0; t < 32; ++t) W2[t] ^= 0x8000000080000000ULL;
  if ((i >> 6) == jh) {
    int p = i - j0;
    #pragma unroll
    for (int t = 0; t < 32; ++t)
      if (t == (p >> 1)) {
        float2 f = up2(W2[t]);
        if (p & 1) f.y += 2.0f; else f.x += 2.0f;
        W2[t] = pk2(f.x, f.y);
      }
  }

  // ---------------- Phase D: Theta += Delta ----------------
  #pragma unroll
  for (int t = 0; t < 16; ++t) {
    float4 a4 = *(const float4*)&sm->sT[i][j0 + 4 * t];
    float4 d4 = *(const float4*)&sm->sD[i][j0 + 4 * t];
    a4.x += d4.x; a4.y += d4.y; a4.z += d4.z; a4.w += d4.w;
    *(float4*)&sm->sT[i][j0 + 4 * t] = a4;
  }
  __syncthreads();

  // ---------------- Phase E prologue: vectors for epoch 0 (c0=0,c1=1) --------
  {
    int r5 = tid & 127;
    if (tid < 128) {
      sm->tv0[0][VIDX(r5)] = (r5 == 0) ? 0.0f : sm->sT[0][r5];
      sm->tv1[0][VIDX(r5)] = (r5 == 1) ? 0.0f : sm->sT[1][r5];
    } else {
      sm->dv0[0][VIDX(r5)] = (r5 == 0) ? 0.0f : sm->sD[0][r5];
      sm->dv1[0][VIDX(r5)] = (r5 == 1) ? 0.0f : sm->sD[1][r5];
    }
  }
  __syncthreads();

  // ---------------- Phase E: blocked-2 column scan (1 barrier / 2 columns) ----
  float F1 = 0.0f, F2 = 0.0f, F3 = 0.0f, F4 = 0.0f;
  #pragma unroll 1
  for (int j = 0; j < 64; ++j) {
    const int cb = j & 1, pb = cb ^ 1;
    const int c0 = 2 * j, c1 = 2 * j + 1;
    const int vc0 = VIDX(c0), vc1 = VIDX(c1);

    // -- loop 1: W += rank-4 (prev epoch); 4 LDS streams only --
    {
      u64 f1p = pk2s(F1), f2p = pk2s(F2), f3p = pk2s(F3), f4p = pk2s(F4);
      #pragma unroll
      for (int t = 0; t < 16; ++t) {
        ulonglong2 gv = *(const ulonglong2*)&sm->gsh0[pb][vb + 4 * t];
        ulonglong2 uv = *(const ulonglong2*)&sm->uv0[pb][vb + 4 * t];
        ulonglong2 gB = *(const ulonglong2*)&sm->gshB[pb][vb + 4 * t];
        ulonglong2 uT = *(const ulonglong2*)&sm->uvT[pb][vb + 4 * t];
        W2[2 * t]     = f2ma(f4p, uT.x, f2ma(f3p, gB.x, f2ma(f2p, uv.x, f2ma(f1p, gv.x, W2[2 * t]))));
        W2[2 * t + 1] = f2ma(f4p, uT.y, f2ma(f3p, gB.y, f2ma(f2p, uv.y, f2ma(f1p, gv.y, W2[2 * t + 1]))));
      }
    }

    // -- loop 2: four matvecs; 4 LDS streams + 8 accumulators --
    u64 ua0[2] = {0, 0}, va0[2] = {0, 0}, ua1[2] = {0, 0}, va1[2] = {0, 0};
    #pragma unroll
    for (int t = 0; t < 16; ++t) {
      ulonglong2 t0 = *(const ulonglong2*)&sm->tv0[cb][vb + 4 * t];
      ulonglong2 d0 = *(const ulonglong2*)&sm->dv0[cb][vb + 4 * t];
      ulonglong2 t1 = *(const ulonglong2*)&sm->tv1[cb][vb + 4 * t];
      ulonglong2 d1 = *(const ulonglong2*)&sm->dv1[cb][vb + 4 * t];
      u64 w0 = W2[2 * t], w1 = W2[2 * t + 1];
      ua0[0] = f2ma(w0, t0.x, ua0[0]);  ua0[1] = f2ma(w1, t0.y, ua0[1]);
      va0[0] = f2ma(w0, d0.x, va0[0]);  va0[1] = f2ma(w1, d0.y, va0[1]);
      ua1[0] = f2ma(w0, t1.x, ua1[0]);  ua1[1] = f2ma(w1, t1.y, ua1[1]);
      va1[0] = f2ma(w0, d1.x, va1[0]);  va1[1] = f2ma(w1, d1.y, va1[1]);
    }
    float2 cu0 = up2(f2add(ua0[0], ua0[1]));  float up0 = cu0.x + cu0.y;
    float2 cv0 = up2(f2add(va0[0], va0[1]));  float vp0 = cv0.x + cv0.y;
    float2 cu1 = up2(f2add(ua1[0], ua1[1]));  float up1 = cu1.x + cu1.y;
    float2 cv1 = up2(f2add(va1[0], va1[1]));  float vp1 = cv1.x + cv1.y;

    // personal values (read pre-barrier from current-parity buffers)
    float ti0 = sm->tv0[cb][VIDX(i)];
    float di0 = sm->dv0[cb][VIDX(i)];
    float ti1 = sm->tv1[cb][VIDX(i)];
    // six reduction seeds
    float s1 = ti0 * up0;   // t0.u0
    float s2 = di0 * vp0;   // d0.v0
    float s3 = ti1 * up1;   // t1.ut
    float s4 = sm->dv1[cb][VIDX(i)] * vp1;  // d1.vt
    float s5 = ti0 * vp1;   // t0.vt
    float s6 = ti0 * up1;   // t0.ut

    // pair combines (partner = tid^1)
    float uf0 = up0 + __shfl_xor_sync(0xffffffffu, up0, 1);
    float vf0 = vp0 + __shfl_xor_sync(0xffffffffu, vp0, 1);
    float uf1 = up1 + __shfl_xor_sync(0xffffffffu, up1, 1);
    float vf1 = vp1 + __shfl_xor_sync(0xffffffffu, vp1, 1);
    if (jh == 0) {
      sm->uv0[cb][VIDX(i)] = uf0 - (i == c0 ? 1.0f : 0.0f);
      sm->uvT[cb][VIDX(i)] = uf1 - (i == c1 ? 1.0f : 0.0f);
      if (i == c0) {
        sm->pt[cb][0] = uf0; sm->pt[cb][1] = vf0;
        sm->pt[cb][2] = uf1; sm->pt[cb][3] = vf1;
      }
      if (i == c1) { sm->pt[cb][4] = uf1; sm->pt[cb][5] = vf1; }
    }
    if (i == c0) {
      #pragma unroll
      for (int t = 0; t < 16; ++t) {
        ulonglong2 o; o.x = W2[2 * t]; o.y = W2[2 * t + 1];
        *(ulonglong2*)&sm->gsh0[cb][vb + 4 * t] = o;
      }
    }
    if (i == c1) {
      #pragma unroll
      for (int t = 0; t < 16; ++t) {
        ulonglong2 o; o.x = W2[2 * t]; o.y = W2[2 * t + 1];
        *(ulonglong2*)&sm->gshB[cb][vb + 4 * t] = o;
      }
    }
    // prefetch next epoch vectors
    if (j < 63) {
      int c0n = c0 + 2, c1n = c0 + 3;
      int r5 = tid & 127;
      if (tid < 128) {
        sm->tv0[pb][VIDX(r5)] = (r5 == c0n) ? 0.0f : sm->sT[c0n][r5];
        sm->tv1[pb][VIDX(r5)] = (r5 == c1n) ? 0.0f : sm->sT[c1n][r5];
      } else {
        sm->dv0[pb][VIDX(r5)] = (r5 == c0n) ? 0.0f : sm->sD[c0n][r5];
        sm->dv1[pb][VIDX(r5)] = (r5 == c1n) ? 0.0f : sm->sD[c1n][r5];
      }
    }

    // six interleaved shfl trees
    #pragma unroll
    for (int o = 16; o > 0; o >>= 1) {
      s1 += __shfl_xor_sync(0xffffffffu, s1, o);
      s2 += __shfl_xor_sync(0xffffffffu, s2, o);
      s3 += __shfl_xor_sync(0xffffffffu, s3, o);
      s4 += __shfl_xor_sync(0xffffffffu, s4, o);
      s5 += __shfl_xor_sync(0xffffffffu, s5, o);
      s6 += __shfl_xor_sync(0xffffffffu, s6, o);
    }
    if ((tid & 31) == 0) {
      int w = tid >> 5;
      sm->red[cb][0][w] = s1; sm->red[cb][1][w] = s2; sm->red[cb][2][w] = s3;
      sm->red[cb][3][w] = s4; sm->red[cb][4][w] = s5; sm->red[cb][5][w] = s6;
    }
    __syncthreads();

    // -- scalars for both columns + next-epoch rank-4 coefficients --
    float r[6];
    #pragma unroll
    for (int q = 0; q < 6; ++q) {
      float4 x0 = *(const float4*)&sm->red[cb][q][0];
      float4 x1 = *(const float4*)&sm->red[cb][q][4];
      r[q] = ((x0.x + x0.y) + (x0.z + x0.w)) + ((x1.x + x1.y) + (x1.z + x1.w));
    }
    float uc0 = sm->pt[cb][0], vc0v = sm->pt[cb][1];
    float A   = sm->pt[cb][2], A2   = sm->pt[cb][3];
    float P5  = sm->pt[cb][4], P6   = sm->pt[cb][5];
    float Tcc0 = sm->sT[c0][c0], Tcc1 = sm->sT[c1][c1];
    float tau  = sm->sT[c0][c1], deld = sm->sD[c0][c1];
    float w22_0 = sm->gsh0[cb][vc0];

    float iw0   = frcp(w22_0);
    float Dden0 = fmaf(Tcc0 + r[1] - r[0], w22_0, uc0 * uc0 - vc0v * vc0v);
    float w22n0 = w22_0 * frcp(Dden0);
    float alpha0 = uc0 * iw0;
    float k4 = w22n0;
    float k2 = -alpha0 * w22n0;
    float k1 = fmaf(-alpha0, k2, -iw0);     // -iw0 + alpha0^2*w22n0

    float a  = sm->gsh0[cb][vc1];
    float bb = sm->uv0[cb][vc1];
    float eh1 = fmaf(k1, a, k2 * bb);
    float eh2 = fmaf(k2, a, k4 * bb);
    float B  = r[5] - tau;                  // u0q . t1
    float B2 = r[4] - deld;                 // u0q . d1
    float uc1 = P5 + eh1 * A + eh2 * B;
    float vc1v = P6 + eh1 * A2 + eh2 * B2;
    float dott1 = r[2] + A  * fmaf(k1, A,  k2 * B)  + B  * fmaf(k2, A,  k4 * B);
    float dotd1 = r[3] + A2 * fmaf(k1, A2, k2 * B2) + B2 * fmaf(k2, A2, k4 * B2);
    float w22_1 = sm->gshB[cb][vc1] + eh1 * a + eh2 * bb;
    float iw1   = frcp(w22_1);
    float Dden1 = fmaf(Tcc1 + dotd1 - dott1, w22_1, uc1 * uc1 - vc1v * vc1v);
    float w22n1 = w22_1 * frcp(Dden1);
    float alpha1 = uc1 * iw1;

    if (tid == 0) {
      sm->diag[c0] = fmaf(-vc0v * vc0v, iw0, Tcc0 + r[1]);
      sm->diag[c1] = fmaf(-vc1v * vc1v, iw1, Tcc1 + dotd1);
    }

    // per-thread next-epoch coefficients
    float g0i = sm->gsh0[cb][VIDX(i)];
    float u0i = sm->uv0[cb][VIDX(i)];
    float gBi = sm->gshB[cb][VIDX(i)];
    float uTi = sm->uvT[cb][VIDX(i)];
    float e2_0 = w22n0 * fmaf(-alpha0, g0i, u0i);
    float e1_0 = fmaf(-alpha0, e2_0, -iw0 * g0i);
    float g1i  = gBi + a * e1_0 + bb * e2_0;
    float u1qi = uTi + A * e1_0 + B * e2_0;
    float e2_1 = w22n1 * fmaf(-alpha1, g1i, u1qi);
    float e1_1 = fmaf(-alpha1, e2_1, -iw1 * g1i);
    float mu1 = fmaf(A, k1, B * k2);
    float mu2 = fmaf(A, k2, B * k4);
    F1 = e1_0 + eh1 * e1_1 + mu1 * e2_1;
    F2 = e2_0 + eh2 * e1_1 + mu2 * e2_1;
    F3 = e1_1;
    F4 = e2_1;
  }
  __syncthreads();

  // ---------------- Phase F: set diagonal, write out ----------------
  if (tid < P) sm->sT[tid][tid] = sm->diag[tid];
  __syncthreads();
  float* Ob = Out + (size_t)b * (P * P);
  for (int idx = tid; idx < P * P; idx += NT)
    Ob[idx] = sm->sT[idx >> 7][idx & 127];
}

extern "C" void kernel_launch(void* const* d_in, const int* in_sizes, int n_in,
                              void* d_out, int out_size)
{
  const float* Theta = (const float*)d_in[0];
  const float* Lw    = (const float*)d_in[1];
  if (n_in >= 2 && in_sizes[0] < in_sizes[1]) {
    const float* t = Theta; Theta = Lw; Lw = t;
  }
  float* Out = (float*)d_out;

  int Bn = in_sizes[0] / (P * P);   // 128

  cudaFuncSetAttribute(spod_kernel,
                       cudaFuncAttributeMaxDynamicSharedMemorySize,
                       (int)sizeof(Smem));
  spod_kernel<<<Bn, NT, sizeof(Smem)>>>(Theta, Lw, Out);
}

// round 17
// speedup vs baseline: 1.5572x; 1.5572x over previous
#include <cuda_runtime.h>

#define P   128
#define NT  256
#define PT  132   // pitch for sT / sD (skewed)
#define PL  130   // pitch for Lsh

typedef unsigned long long u64;

struct __align__(16) Smem {
  float sT[P][PT];     // Theta (orig), later Theta+Delta (symmetric)
  float sD[P][PT];     // Tc buffer, later Delta (symmetric, zero diag)
  float Lsh[P][PL];    // L_w (127x127, row 127 zeroed)
  float rowA[2][PT];   // sweep pivot row k   (with [k]   -= 1)
  float rowB[2][PT];   // sweep pivot row k+1 (with [k+1] -= 1)
  float dvec[2][PT];   // scan: d-hat (double-buffered, gapped)
  float gsh[2][PT];    // scan: W row c (double-buffered, gapped)
  float red[2][8];     // block reduction partials
  float pt[2][2];      // v_c
  float diag[P];
};

// gapped index: halves offset by +4 floats -> warp halves hit different banks
__device__ __forceinline__ int VIDX(int x) { return x + ((x >> 6) << 2); }

__device__ __forceinline__ u64 pk2s(float x) {
  u64 r; asm("mov.b64 %0,{%1,%1};" : "=l"(r) : "f"(x)); return r;
}
__device__ __forceinline__ u64 pk2(float x, float y) {
  u64 r; asm("mov.b64 %0,{%1,%2};" : "=l"(r) : "f"(x), "f"(y)); return r;
}
__device__ __forceinline__ float2 up2(u64 a) {
  float2 f; asm("mov.b64 {%0,%1},%2;" : "=f"(f.x), "=f"(f.y) : "l"(a)); return f;
}
__device__ __forceinline__ u64 f2ma(u64 a, u64 b, u64 c) {
  u64 d; asm("fma.rn.f32x2 %0,%1,%2,%3;" : "=l"(d) : "l"(a), "l"(b), "l"(c));
  return d;
}
__device__ __forceinline__ u64 f2add(u64 a, u64 b) {
  u64 d; asm("add.rn.f32x2 %0,%1,%2;" : "=l"(d) : "l"(a), "l"(b));
  return d;
}
__device__ __forceinline__ float frcp(float x) {
  float r; asm("rcp.approx.f32 %0,%1;" : "=f"(r) : "f"(x)); return r;
}

__global__ void __launch_bounds__(NT, 1)
spod_kernel(const float* __restrict__ Theta,
            const float* __restrict__ Lw,
            float* __restrict__ Out)
{
  extern __shared__ __align__(16) float smraw[];
  Smem* sm = reinterpret_cast<Smem*>(smraw);

  const int tid = threadIdx.x;
  const int b   = blockIdx.x;
  const int i   = tid >> 1;      // row owned by this thread
  const int jh  = tid & 1;       // which 64-column half
  const int j0  = jh << 6;       // 0 or 64
  const int vb  = jh ? 68 : 0;   // VIDX(j0)

  const float* Tin = Theta + (size_t)b * (P * P);

  // ---------------- Phase A: load Theta, L_w (coalesced) ----------------
  for (int idx = tid; idx < P * P; idx += NT)
    sm->sT[idx >> 7][idx & 127] = Tin[idx];
  for (int idx = tid; idx < 127 * 127; idx += NT) {
    int r = idx / 127;
    sm->Lsh[r][idx - r * 127] = Lw[idx];
  }
  if (tid < PL) sm->Lsh[127][tid] = 0.0f;
  if (tid < PT) sm->gsh[1][tid] = 0.0f;   // step-0 previous-g buffer
  __syncthreads();

  // ---------------- Phase B0: Tc[m][c] = Theta[m + (m>=c)][c] ----------------
  for (int idx = tid; idx < 127 * P; idx += NT) {
    int m = idx >> 7, c = idx & 127;
    sm->sD[m][c] = sm->sT[m + (m >= c)][c];
  }
  __syncthreads();

  // ---------------- Phase B1: Y = Lsh @ Tc (packed f32x2) ----------------
  const int tj = tid >> 4, ti = tid & 15;
  const int jr = tj * 8, ic = ti * 8;
  u64 acc2[8][4];
  #pragma unroll
  for (int r = 0; r < 8; ++r)
    #pragma unroll
    for (int s = 0; s < 4; ++s) acc2[r][s] = 0ULL;

  #pragma unroll 1
  for (int m = 0; m < 127; ++m) {
    ulonglong2 ta = *(const ulonglong2*)&sm->sD[m][ic];
    ulonglong2 tb = *(const ulonglong2*)&sm->sD[m][ic + 4];
    #pragma unroll
    for (int r = 0; r < 8; ++r) {
      u64 lr = pk2s(sm->Lsh[jr + r][m]);
      acc2[r][0] = f2ma(lr, ta.x, acc2[r][0]);
      acc2[r][1] = f2ma(lr, ta.y, acc2[r][1]);
      acc2[r][2] = f2ma(lr, tb.x, acc2[r][2]);
      acc2[r][3] = f2ma(lr, tb.y, acc2[r][3]);
    }
  }
  __syncthreads();

  // ---------------- Phase B2: Delta (symmetric) into sD ----------------
  #pragma unroll
  for (int r = 0; r < 8; ++r) {
    int j = jr + r;
    #pragma unroll
    for (int s = 0; s < 4; ++s) {
      float2 f = up2(acc2[r][s]);
      int i0 = ic + 2 * s, i1 = i0 + 1;
      if (j < i0) { float d0 = f.x - sm->sT[j][i0]; sm->sD[i0][j] = d0; sm->sD[j][i0] = d0; }
      if (j < i1) { float d1 = f.y - sm->sT[j][i1]; sm->sD[i1][j] = d1; sm->sD[j][i1] = d1; }
    }
  }
  if (tid < P) sm->sD[tid][tid] = 0.0f;
  __syncthreads();

  // ---------------- Phase C: W = inv(Theta), 2-pivot blocked sweep ----------------
  u64 W2[32];
  #pragma unroll
  for (int t = 0; t < 16; ++t) {
    ulonglong2 v = *(const ulonglong2*)&sm->sT[i][j0 + 4 * t];
    W2[2 * t] = v.x; W2[2 * t + 1] = v.y;
  }

  #pragma unroll 1
  for (int k = 0; k < P; k += 2) {
    const int buf = (k >> 1) & 1;
    if (i == k || i == k + 1) {
      float* dst = (i == k) ? sm->rowA[buf] : sm->rowB[buf];
      #pragma unroll
      for (int t = 0; t < 16; ++t) {
        ulonglong2 o; o.x = W2[2 * t]; o.y = W2[2 * t + 1];
        *(ulonglong2*)&dst[vb + 4 * t] = o;
      }
      if ((i >> 6) == jh)            // my half holds column i: [i] -= 1 fixup
        dst[VIDX(i)] -= 1.0f;
    }
    __syncthreads();

    float a_k  = sm->rowA[buf][VIDX(k)];      // d00 - 1
    float a_k1 = sm->rowA[buf][VIDX(k + 1)];  // d01
    float b_k1 = sm->rowB[buf][VIDX(k + 1)];  // d11 - 1
    float d00 = a_k + 1.0f, d01 = a_k1, d11 = b_k1 + 1.0f;
    float rdet = frcp(fmaf(d00, d11, -d01 * d01));
    float i00 = d11 * rdet, i01 = -d01 * rdet, i11 = d00 * rdet;
    float c1w = sm->rowA[buf][VIDX(i)];
    float c2w = sm->rowB[buf][VIDX(i)];
    float g1 = fmaf(c1w, i00, c2w * i01);
    float g2 = fmaf(c1w, i01, c2w * i11);
    u64 ng1 = pk2s(-g1), ng2 = pk2s(-g2);
    #pragma unroll
    for (int t = 0; t < 16; ++t) {
      ulonglong2 rA = *(const ulonglong2*)&sm->rowA[buf][vb + 4 * t];
      ulonglong2 rB = *(const ulonglong2*)&sm->rowB[buf][vb + 4 * t];
      W2[2 * t]     = f2ma(ng2, rB.x, f2ma(ng1, rA.x, W2[2 * t]));
      W2[2 * t + 1] = f2ma(ng2, rB.y, f2ma(ng1, rA.y, W2[2 * t + 1]));
    }
  }

  // negate (sweep gives -A^{-1}), then fix the constant +2 pivot-diag error
  #pragma unroll
  for (int t = 0; t < 32; ++t) W2[t] ^= 0x8000000080000000ULL;
  if ((i >> 6) == jh) {
    int p = i - j0;
    #pragma unroll
    for (int t = 0; t < 32; ++t)
      if (t == (p >> 1)) {
        float2 f = up2(W2[t]);
        if (p & 1) f.y += 2.0f; else f.x += 2.0f;
        W2[t] = pk2(f.x, f.y);
      }
  }

  // ---------------- Phase D: Theta += Delta ----------------
  #pragma unroll
  for (int t = 0; t < 16; ++t) {
    float4 a4 = *(const float4*)&sm->sT[i][j0 + 4 * t];
    float4 d4 = *(const float4*)&sm->sD[i][j0 + 4 * t];
    a4.x += d4.x; a4.y += d4.y; a4.z += d4.z; a4.w += d4.w;
    *(float4*)&sm->sT[i][j0 + 4 * t] = a4;
  }
  __syncthreads();

  // ---------------- Phase E prologue: d-hat for c=0 ----------------
  if (tid < 128)
    sm->dvec[0][VIDX(tid)] = (tid == 0) ? 0.0f : sm->sD[0][tid];
  __syncthreads();

  // ---------------- Phase E: Sherman-Morrison diagonal-update scan ----------
  // Per step: W_c = W_{c-1} + coef_{c-1} * g_{c-1} (rank-1, lazily applied),
  // v = W_c d-hat_c, delta = d.v - v_c^2/w22, t22n = Tcc + delta,
  // rho = delta/(1+delta*w22), coef_i = -rho * g_i.
  float coef = 0.0f;
  #pragma unroll 1
  for (int c = 0; c < P; ++c) {
    const int cb = c & 1, pb = cb ^ 1;
    const int vc = VIDX(c);
    u64 cfp = pk2s(coef);

    // fused: W += coef * g_prev, then va += W * d-hat
    u64 va0 = 0ULL, va1 = 0ULL;
    #pragma unroll
    for (int t = 0; t < 16; ++t) {
      ulonglong2 gv = *(const ulonglong2*)&sm->gsh[pb][vb + 4 * t];
      u64 w0 = f2ma(cfp, gv.x, W2[2 * t]);
      u64 w1 = f2ma(cfp, gv.y, W2[2 * t + 1]);
      W2[2 * t] = w0; W2[2 * t + 1] = w1;
      ulonglong2 dv = *(const ulonglong2*)&sm->dvec[cb][vb + 4 * t];
      va0 = f2ma(w0, dv.x, va0);
      va1 = f2ma(w1, dv.y, va1);
    }
    float2 cv = up2(f2add(va0, va1));
    float vp = cv.x + cv.y;

    float di = sm->dvec[cb][VIDX(i)];
    float s  = di * vp;                      // block-sums to d-hat . v

    // pair combine: v_c needed only by pair c
    float vf = vp + __shfl_xor_sync(0xffffffffu, vp, 1);
    if (i == c) {
      if (jh == 0) sm->pt[cb][0] = vf;
      // publish updated W row c (the g vector for scalars + next update)
      #pragma unroll
      for (int t = 0; t < 16; ++t) {
        ulonglong2 o; o.x = W2[2 * t]; o.y = W2[2 * t + 1];
        *(ulonglong2*)&sm->gsh[cb][vb + 4 * t] = o;
      }
    }
    // prefetch next d-hat
    int cn = c + 1;
    if (cn < P && tid < 128)
      sm->dvec[pb][VIDX(tid)] = (tid == cn) ? 0.0f : sm->sD[cn][tid];

    #pragma unroll
    for (int o = 16; o > 0; o >>= 1)
      s += __shfl_xor_sync(0xffffffffu, s, o);
    if ((tid & 31) == 0) sm->red[cb][tid >> 5] = s;
    __syncthreads();

    // scalars (all threads redundantly)
    float4 r0 = *(const float4*)&sm->red[cb][0];
    float4 r1 = *(const float4*)&sm->red[cb][4];
    float dotd = ((r0.x + r0.y) + (r0.z + r0.w)) + ((r1.x + r1.y) + (r1.z + r1.w));
    float vcv = sm->pt[cb][0];
    float w22 = sm->gsh[cb][vc];
    float Tcc = sm->sT[c][c];
    float iw  = frcp(w22);
    float q   = fmaf(dotd, w22, -vcv * vcv);   // = delta * w22
    float rho = q * iw * frcp(1.0f + q);       // two independent rcps
    float gi  = sm->gsh[cb][VIDX(i)];
    coef = -rho * gi;
    if (tid == 0) sm->diag[c] = fmaf(q, iw, Tcc);   // Tcc + delta
  }
  __syncthreads();

  // ---------------- Phase F: set diagonal, write out ----------------
  if (tid < P) sm->sT[tid][tid] = sm->diag[tid];
  __syncthreads();
  float* Ob = Out + (size_t)b * (P * P);
  for (int idx = tid; idx < P * P; idx += NT)
    Ob[idx] = sm->sT[idx >> 7][idx & 127];
}

extern "C" void kernel_launch(void* const* d_in, const int* in_sizes, int n_in,
                              void* d_out, int out_size)
{
  const float* Theta = (const float*)d_in[0];
  const float* Lw    = (const float*)d_in[1];
  if (n_in >= 2 && in_sizes[0] < in_sizes[1]) {
    const float* t = Theta; Theta = Lw; Lw = t;
  }
  float* Out = (float*)d_out;

  int Bn = in_sizes[0] / (P * P);   // 128

  cudaFuncSetAttribute(spod_kernel,
                       cudaFuncAttributeMaxDynamicSharedMemorySize,
                       (int)sizeof(Smem));
  spod_kernel<<<Bn, NT, sizeof(Smem)>>>(Theta, Lw, Out);
}